// round 6
// baseline (speedup 1.0000x reference)
#include <cuda_runtime.h>
#include <cuda_bf16.h>
#include <cstdint>
#include <cstddef>

#define N_NODES 50000
#define N_PADR  50048
#define N_EDGES_MAX 800000
#define D_V 133
#define D_E 14
#define D_H 300
#define GN  300
#define KP_V 160               // D_V padded to mult of 32
#define KP_H 320               // D_H padded to mult of 32
#define NPADW 384              // weight rows padded to 3*128

// ---------------- scratch (static device globals; no allocation) ------------
__device__ __align__(256) float g_H0[(size_t)N_NODES * D_H];
__device__ __align__(256) float g_Hs[(size_t)N_NODES * D_H];
__device__ __align__(256) float g_Cs[(size_t)N_NODES * D_H];
__device__ __align__(256) float g_Ps[(size_t)N_NODES * D_H];
__device__ __align__(256) float g_SE[(size_t)N_NODES * D_E];
__device__ __align__(256) __nv_bfloat16 g_Ahi[(size_t)N_PADR * KP_H];
__device__ __align__(256) __nv_bfloat16 g_Alo[(size_t)N_PADR * KP_H];
__device__ __align__(256) __nv_bfloat16 g_Vhi[(size_t)N_PADR * KP_V];
__device__ __align__(256) __nv_bfloat16 g_Vlo[(size_t)N_PADR * KP_V];
__device__ __align__(256) __nv_bfloat16 g_Wihi[NPADW * KP_V];
__device__ __align__(256) __nv_bfloat16 g_Wilo[NPADW * KP_V];
__device__ __align__(256) __nv_bfloat16 g_WoVhi[NPADW * KP_V];
__device__ __align__(256) __nv_bfloat16 g_WoVlo[NPADW * KP_V];
__device__ __align__(256) __nv_bfloat16 g_WhHhi[NPADW * KP_H];
__device__ __align__(256) __nv_bfloat16 g_WhHlo[NPADW * KP_H];
__device__ __align__(256) __nv_bfloat16 g_WoHhi[NPADW * KP_H];
__device__ __align__(256) __nv_bfloat16 g_WoHlo[NPADW * KP_H];
__device__ int   g_deg[N_NODES];
__device__ int   g_cnt[N_NODES];
__device__ int   g_rowptr[N_NODES + 1];
__device__ int   g_srcA[N_EDGES_MAX];
__device__ int   g_dstA[N_EDGES_MAX];
__device__ int   g_csr[N_EDGES_MAX];
__device__ int   g_blk[256];
__device__ int   g_blkoff[256];
__device__ int   g_is64;

// ======================= PTX helpers (family-safe only) =====================
__device__ __forceinline__ uint32_t s2u(const void* p) {
    uint32_t a;
    asm("{ .reg .u64 t; cvta.to.shared.u64 t, %1; cvt.u32.u64 %0, t; }"
        : "=r"(a) : "l"(p));
    return a;
}
#define CPA16(sa, ga) \
    asm volatile("cp.async.cg.shared.global [%0], [%1], 16;" :: "r"(sa), "l"(ga) : "memory")
#define CP_COMMIT() asm volatile("cp.async.commit_group;" ::: "memory")
template <int N>
__device__ __forceinline__ void cp_wait() {
    asm volatile("cp.async.wait_group %0;" :: "n"(N) : "memory");
}
#define LDSM_X4(r0, r1, r2, r3, addr) \
    asm volatile("ldmatrix.sync.aligned.m8n8.x4.shared.b16 {%0,%1,%2,%3}, [%4];" \
        : "=r"(r0), "=r"(r1), "=r"(r2), "=r"(r3) : "r"(addr))
#define MMA16816(d, a, b) \
    asm volatile("mma.sync.aligned.m16n8k16.row.col.f32.bf16.bf16.f32 " \
        "{%0,%1,%2,%3}, {%4,%5,%6,%7}, {%8,%9}, {%0,%1,%2,%3};" \
        : "+f"((d)[0]), "+f"((d)[1]), "+f"((d)[2]), "+f"((d)[3]) \
        : "r"((a)[0]), "r"((a)[1]), "r"((a)[2]), "r"((a)[3]), \
          "r"((b)[0]), "r"((b)[1]))

#define ROWB   80                  // smem row pitch (bytes) for 32-bf16 rows
#define MAT_B  (128 * ROWB)        // 10240 bytes per matrix tile
#define STAGE_B (4 * MAT_B)        // Ahi, Alo, Bhi, Blo
#define TG_SMEM (2 * STAGE_B)      // 81920 (also covers 128x136 f32 epilogue)

// ======================= setup kernels ======================================
__global__ void detect_k(const unsigned long long* __restrict__ p, int n64) {
    if (blockIdx.x | threadIdx.x) return;
    int is64 = 1;
    int lim = n64 < 64 ? n64 : 64;
    for (int i = 0; i < lim; i++)
        if (p[i] >= (1ULL << 32)) { is64 = 0; break; }
    g_is64 = is64;
}

__global__ void zero_k() {
    int i = blockIdx.x * blockDim.x + threadIdx.x;
    if (i < N_NODES) { g_deg[i] = 0; g_cnt[i] = 0; }
    if (i < N_NODES * D_E) g_SE[i] = 0.f;
}

__global__ void convert_hist_k(const void* __restrict__ ei, int nE) {
    int e = blockIdx.x * blockDim.x + threadIdx.x;
    if (e >= nE) return;
    int s, d;
    if (g_is64) {
        const long long* p = (const long long*)ei;
        s = (int)p[e]; d = (int)p[nE + e];
    } else {
        const int* p = (const int*)ei;
        s = p[e]; d = p[nE + e];
    }
    g_srcA[e] = s;
    g_dstA[e] = d;
    atomicAdd(&g_deg[d], 1);
}

__global__ void scan1_k() {
    __shared__ int sm[256];
    int t = threadIdx.x, b = blockIdx.x;
    int i = b * 256 + t;
    sm[t] = (i < N_NODES) ? g_deg[i] : 0;
    __syncthreads();
    for (int off = 128; off; off >>= 1) {
        if (t < off) sm[t] += sm[t + off];
        __syncthreads();
    }
    if (t == 0) g_blk[b] = sm[0];
}
__global__ void scan2_k(int nb) {
    __shared__ int sm[256];
    int t = threadIdx.x;
    int v = (t < nb) ? g_blk[t] : 0;
    sm[t] = v;
    __syncthreads();
    for (int off = 1; off < 256; off <<= 1) {
        int u = (t >= off) ? sm[t - off] : 0;
        __syncthreads();
        sm[t] += u;
        __syncthreads();
    }
    if (t < nb) g_blkoff[t] = sm[t] - v;
}
__global__ void scan3_k() {
    __shared__ int sm[256];
    int t = threadIdx.x, b = blockIdx.x;
    int i = b * 256 + t;
    int v = (i < N_NODES) ? g_deg[i] : 0;
    sm[t] = v;
    __syncthreads();
    for (int off = 1; off < 256; off <<= 1) {
        int u = (t >= off) ? sm[t - off] : 0;
        __syncthreads();
        sm[t] += u;
        __syncthreads();
    }
    int excl = sm[t] - v + g_blkoff[b];
    if (i < N_NODES) g_rowptr[i] = excl;
    if (i == N_NODES - 1) g_rowptr[N_NODES] = excl + v;
}

__global__ void csr_fill_k(int nE) {
    int e = blockIdx.x * blockDim.x + threadIdx.x;
    if (e >= nE) return;
    int d = g_dstA[e];
    int pos = atomicAdd(&g_cnt[d], 1);
    g_csr[g_rowptr[d] + pos] = g_srcA[e];
}

__global__ void se_scatter_k(const float* __restrict__ E, int nE) {
    int e = blockIdx.x * blockDim.x + threadIdx.x;
    if (e >= nE) return;
    int d = g_dstA[e];
    float* base = &g_SE[(size_t)d * D_E];
    const float* src = &E[(size_t)e * D_E];
#pragma unroll
    for (int k = 0; k < D_E; k++) atomicAdd(base + k, src[k]);
}

// ======================= bf16 split helpers =================================
__device__ __forceinline__ void split4(float4 v, uint2& hi, uint2& lo) {
    __nv_bfloat16 hx = __float2bfloat16(v.x), hy = __float2bfloat16(v.y);
    __nv_bfloat16 hz = __float2bfloat16(v.z), hw = __float2bfloat16(v.w);
    __nv_bfloat16 lx = __float2bfloat16(v.x - __bfloat162float(hx));
    __nv_bfloat16 ly = __float2bfloat16(v.y - __bfloat162float(hy));
    __nv_bfloat16 lz = __float2bfloat16(v.z - __bfloat162float(hz));
    __nv_bfloat16 lw = __float2bfloat16(v.w - __bfloat162float(hw));
    hi.x = (uint32_t)__bfloat16_as_ushort(hx) | ((uint32_t)__bfloat16_as_ushort(hy) << 16);
    hi.y = (uint32_t)__bfloat16_as_ushort(hz) | ((uint32_t)__bfloat16_as_ushort(hw) << 16);
    lo.x = (uint32_t)__bfloat16_as_ushort(lx) | ((uint32_t)__bfloat16_as_ushort(ly) << 16);
    lo.y = (uint32_t)__bfloat16_as_ushort(lz) | ((uint32_t)__bfloat16_as_ushort(lw) << 16);
}

__global__ void splitV_k(const float* __restrict__ V, int M) {
    int idx = blockIdx.x * blockDim.x + threadIdx.x;
    if (idx >= M * KP_V) return;
    int m = idx / KP_V, k = idx - m * KP_V;
    float x = (k < D_V) ? V[(size_t)m * D_V + k] : 0.f;
    __nv_bfloat16 h = __float2bfloat16(x);
    g_Vhi[idx] = h;
    g_Vlo[idx] = __float2bfloat16(x - __bfloat162float(h));
}

__global__ void prepW_k(const float* __restrict__ W, int ldW, int colOff, int K,
                        int Kpad, __nv_bfloat16* __restrict__ hi,
                        __nv_bfloat16* __restrict__ lo) {
    int idx = blockIdx.x * blockDim.x + threadIdx.x;
    if (idx >= NPADW * Kpad) return;
    int n = idx / Kpad, k = idx - n * Kpad;
    float x = (n < GN && k < K) ? W[(size_t)n * ldW + colOff + k] : 0.f;
    __nv_bfloat16 h = __float2bfloat16(x);
    hi[idx] = h;
    lo[idx] = __float2bfloat16(x - __bfloat162float(h));
}

// ------- gather + segment-sum (float4 vectorized), emits bf16 hi/lo --------
__global__ __launch_bounds__(256) void seg_sum_split_k(const float* __restrict__ Hin) {
    int gw = (blockIdx.x * blockDim.x + threadIdx.x) >> 5;
    int lane = threadIdx.x & 31;
    if (gw >= N_NODES) return;
    int beg = g_rowptr[gw], end = g_rowptr[gw + 1];
    bool v2 = lane < 11;                      // float4 idx lane+64 < 75
    float4 a0 = {0.f, 0.f, 0.f, 0.f}, a1 = a0, a2 = a0;

    int i = beg;
    for (; i + 1 < end; i += 2) {
        const float4* r0 = (const float4*)(Hin + (size_t)g_csr[i] * D_H);
        const float4* r1 = (const float4*)(Hin + (size_t)g_csr[i + 1] * D_H);
        float4 x0 = __ldg(&r0[lane]),      y0 = __ldg(&r1[lane]);
        float4 x1 = __ldg(&r0[lane + 32]), y1 = __ldg(&r1[lane + 32]);
        a0.x += x0.x + y0.x; a0.y += x0.y + y0.y; a0.z += x0.z + y0.z; a0.w += x0.w + y0.w;
        a1.x += x1.x + y1.x; a1.y += x1.y + y1.y; a1.z += x1.z + y1.z; a1.w += x1.w + y1.w;
        if (v2) {
            float4 x2 = __ldg(&r0[lane + 64]), y2 = __ldg(&r1[lane + 64]);
            a2.x += x2.x + y2.x; a2.y += x2.y + y2.y;
            a2.z += x2.z + y2.z; a2.w += x2.w + y2.w;
        }
    }
    if (i < end) {
        const float4* r0 = (const float4*)(Hin + (size_t)g_csr[i] * D_H);
        float4 x0 = __ldg(&r0[lane]), x1 = __ldg(&r0[lane + 32]);
        a0.x += x0.x; a0.y += x0.y; a0.z += x0.z; a0.w += x0.w;
        a1.x += x1.x; a1.y += x1.y; a1.z += x1.z; a1.w += x1.w;
        if (v2) {
            float4 x2 = __ldg(&r0[lane + 64]);
            a2.x += x2.x; a2.y += x2.y; a2.z += x2.z; a2.w += x2.w;
        }
    }

    size_t o = (size_t)gw * KP_H;
    uint2* Hv = (uint2*)(g_Ahi + o);
    uint2* Lv = (uint2*)(g_Alo + o);
    uint2 h, l;
    split4(a0, h, l); Hv[lane] = h;      Lv[lane] = l;
    split4(a1, h, l); Hv[lane + 32] = h; Lv[lane + 32] = l;
    if (v2) { split4(a2, h, l); Hv[lane + 64] = h; Lv[lane + 64] = l; }
    else if (lane < 16) {                 // float4 idx 75..79 -> zero pad
        uint2 z = {0u, 0u};
        Hv[lane + 64] = z; Lv[lane + 64] = z;
    }
}

// ======================= SIMT SGEMM (only for Cs, K=14) =====================
__global__ __launch_bounds__(256) void sgemm_k(
    const float* __restrict__ X, int K, int M,
    const float* __restrict__ W, int ldW, int colOff,
    const float* __restrict__ bias, const int* __restrict__ degv,
    float* __restrict__ Out)
{
    __shared__ __align__(16) float As[8][128];
    __shared__ __align__(16) float Bs[8][128];
    int tid = threadIdx.x;
    int m0 = blockIdx.x * 128;
    int n0 = blockIdx.y * 128;
    int xr = tid >> 3, xc = tid & 7;
    int tx = tid & 15, ty = tid >> 4;
    int mA = ty * 4, mB = 64 + ty * 4;
    int nA = tx * 4, nB = 64 + tx * 4;
    float acc[8][8] = {};

    for (int k0 = 0; k0 < K; k0 += 8) {
#pragma unroll
        for (int i = 0; i < 4; i++) {
            int m = xr + i * 32;
            int gm = m0 + m, gk = k0 + xc;
            As[xc][m] = (gm < M && gk < K) ? X[(size_t)gm * K + gk] : 0.f;
        }
#pragma unroll
        for (int i = 0; i < 4; i++) {
            int n = xr + i * 32;
            int gn = n0 + n, gk = k0 + xc;
            Bs[xc][n] = (gn < GN && gk < K) ? W[(size_t)gn * ldW + colOff + gk] : 0.f;
        }
        __syncthreads();
#pragma unroll
        for (int k = 0; k < 8; k++) {
            float4 q0 = *(const float4*)&As[k][mA];
            float4 q1 = *(const float4*)&As[k][mB];
            float4 b0 = *(const float4*)&Bs[k][nA];
            float4 b1 = *(const float4*)&Bs[k][nB];
            float av[8] = {q0.x, q0.y, q0.z, q0.w, q1.x, q1.y, q1.z, q1.w};
            float bv[8] = {b0.x, b0.y, b0.z, b0.w, b1.x, b1.y, b1.z, b1.w};
#pragma unroll
            for (int i = 0; i < 8; i++)
#pragma unroll
                for (int j = 0; j < 8; j++)
                    acc[i][j] += av[i] * bv[j];
        }
        __syncthreads();
    }
#pragma unroll
    for (int i = 0; i < 8; i++) {
        int m = m0 + ((i < 4) ? (ty * 4 + i) : (64 + ty * 4 + (i - 4)));
        if (m >= M) continue;
        float degf = degv ? (float)degv[m] : 1.f;
#pragma unroll
        for (int j = 0; j < 8; j++) {
            int n = n0 + ((j < 4) ? (tx * 4 + j) : (64 + tx * 4 + (j - 4)));
            if (n >= GN) continue;
            float v = acc[i][j] + degf * bias[n];
            Out[(size_t)m * GN + n] = v;
        }
    }
}

// ======================= HMMA bf16x3 GEMM ===================================
__global__ void __launch_bounds__(256) tgemm_k(
    const __nv_bfloat16* __restrict__ Xhi, const __nv_bfloat16* __restrict__ Xlo,
    const __nv_bfloat16* __restrict__ Whi, const __nv_bfloat16* __restrict__ Wlo,
    int Kpad, int nchunks, int M,
    const float* __restrict__ bias, const float* __restrict__ add1,
    const float* __restrict__ add2, int relu, float* __restrict__ Out)
{
    extern __shared__ __align__(16) char smem[];
    uint32_t sb = s2u(smem);
    int tid = threadIdx.x, wid = tid >> 5, lane = tid & 31;
    int wm = wid >> 2, wn = wid & 3;       // 2 x 4 warp grid, warp tile 64x32
    int m0 = blockIdx.x * 128, n0 = blockIdx.y * 128;

    size_t ldb = (size_t)Kpad * 2;
    const char* gsrc[4];
    gsrc[0] = (const char*)(Xhi + (size_t)m0 * Kpad);
    gsrc[1] = (const char*)(Xlo + (size_t)m0 * Kpad);
    gsrc[2] = (const char*)(Whi + (size_t)n0 * Kpad);
    gsrc[3] = (const char*)(Wlo + (size_t)n0 * Kpad);

    float acc[4][4][4] = {};

#define LOAD_STAGE(s, c)                                                       \
    do {                                                                       \
        uint32_t _base = sb + (uint32_t)(s) * STAGE_B;                         \
        _Pragma("unroll")                                                      \
        for (int _t = 0; _t < 8; _t++) {                                       \
            int _id = _t * 256 + tid;                                          \
            int _mat = _id >> 9;                                               \
            int _r = (_id >> 2) & 127;                                         \
            int _q = _id & 3;                                                  \
            uint32_t _so = _base + _mat * MAT_B + _r * ROWB + _q * 16;         \
            const char* _g = gsrc[_mat] + (size_t)_r * ldb + (c) * 64 + _q * 16; \
            CPA16(_so, _g);                                                    \
        }                                                                      \
    } while (0)

    LOAD_STAGE(0, 0);
    CP_COMMIT();

    for (int i = 0; i < nchunks; i++) {
        if (i + 1 < nchunks) {
            LOAD_STAGE((i + 1) & 1, i + 1);
            CP_COMMIT();
            cp_wait<1>();
        } else {
            cp_wait<0>();
        }
        __syncthreads();
        uint32_t stb = sb + (uint32_t)(i & 1) * STAGE_B;

#pragma unroll
        for (int kk = 0; kk < 2; kk++) {
            int k0 = kk * 16;
            int ar = lane & 7, sel = lane >> 3;
            int arow = ((sel & 1) ? 8 : 0) + ar;
            int akof = (k0 + ((sel >> 1) ? 8 : 0)) * 2;
            uint32_t ah[4][4], al[4][4];
#pragma unroll
            for (int mt = 0; mt < 4; mt++) {
                uint32_t ad = stb + (wm * 64 + mt * 16 + arow) * ROWB + akof;
                LDSM_X4(ah[mt][0], ah[mt][1], ah[mt][2], ah[mt][3], ad);
                LDSM_X4(al[mt][0], al[mt][1], al[mt][2], al[mt][3], ad + MAT_B);
            }
            int brow = ((sel >> 1) ? 8 : 0) + ar;
            int bkof = (k0 + ((sel & 1) ? 8 : 0)) * 2;
            uint32_t bh[4][2], bl[4][2];
#pragma unroll
            for (int p = 0; p < 2; p++) {
                uint32_t bd = stb + 2 * MAT_B + (wn * 32 + p * 16 + brow) * ROWB + bkof;
                uint32_t r0, r1, r2, r3;
                LDSM_X4(r0, r1, r2, r3, bd);
                bh[p * 2][0] = r0; bh[p * 2][1] = r1;
                bh[p * 2 + 1][0] = r2; bh[p * 2 + 1][1] = r3;
                LDSM_X4(r0, r1, r2, r3, bd + MAT_B);
                bl[p * 2][0] = r0; bl[p * 2][1] = r1;
                bl[p * 2 + 1][0] = r2; bl[p * 2 + 1][1] = r3;
            }
#pragma unroll
            for (int mt = 0; mt < 4; mt++)
#pragma unroll
                for (int nt = 0; nt < 4; nt++) {
                    MMA16816(acc[mt][nt], ah[mt], bh[nt]);
                    MMA16816(acc[mt][nt], ah[mt], bl[nt]);
                    MMA16816(acc[mt][nt], al[mt], bh[nt]);
                }
        }
        __syncthreads();
    }
#undef LOAD_STAGE

    float* Ds = (float*)smem;          // 128 x 136 floats
    int g = lane >> 2, tg = lane & 3;
#pragma unroll
    for (int mt = 0; mt < 4; mt++)
#pragma unroll
        for (int nt = 0; nt < 4; nt++) {
            int row = wm * 64 + mt * 16 + g;
            int col = wn * 32 + nt * 8 + tg * 2;
            Ds[row * 136 + col]           = acc[mt][nt][0];
            Ds[row * 136 + col + 1]       = acc[mt][nt][1];
            Ds[(row + 8) * 136 + col]     = acc[mt][nt][2];
            Ds[(row + 8) * 136 + col + 1] = acc[mt][nt][3];
        }
    __syncthreads();

    int col = tid & 127, rh = tid >> 7;
    int n = n0 + col;
    bool nv = n < GN;
    float bv = (bias && nv) ? bias[n] : 0.f;
    for (int r = rh * 64; r < rh * 64 + 64; r++) {
        int gm = m0 + r;
        if (gm >= M) break;
        if (nv) {
            float v = Ds[r * 136 + col] + bv;
            if (add1) v += add1[(size_t)gm * GN + n];
            if (add2) v += add2[(size_t)gm * GN + n];
            if (relu) v = fmaxf(v, 0.f);
            Out[(size_t)gm * GN + n] = v;
        }
    }
}

// ======================= host orchestration =================================
extern "C" void kernel_launch(void* const* d_in, const int* in_sizes, int n_in,
                              void* d_out, int out_size) {
    const float* V   = (const float*)d_in[0];
    const float* E   = (const float*)d_in[1];
    const void*  EI  = d_in[2];
    const float* W_i = (const float*)d_in[3];
    const float* b_i = (const float*)d_in[4];
    const float* W_h = (const float*)d_in[5];
    const float* b_h = (const float*)d_in[6];
    const float* W_o = (const float*)d_in[7];
    const float* b_o = (const float*)d_in[8];
    float* out = (float*)d_out;

    int nE = in_sizes[2] / 2;
    int M  = in_sizes[0] / D_V;   // 50000

    float *H0, *Hs, *Cs, *Ps, *SE;
    int *deg;
    __nv_bfloat16 *Ahi, *Alo, *Vhi, *Vlo;
    __nv_bfloat16 *Wihi, *Wilo, *WoVhi, *WoVlo, *WhHhi, *WhHlo, *WoHhi, *WoHlo;
    cudaGetSymbolAddress((void**)&H0, g_H0);
    cudaGetSymbolAddress((void**)&Hs, g_Hs);
    cudaGetSymbolAddress((void**)&Cs, g_Cs);
    cudaGetSymbolAddress((void**)&Ps, g_Ps);
    cudaGetSymbolAddress((void**)&SE, g_SE);
    cudaGetSymbolAddress((void**)&deg, g_deg);
    cudaGetSymbolAddress((void**)&Ahi, g_Ahi);
    cudaGetSymbolAddress((void**)&Alo, g_Alo);
    cudaGetSymbolAddress((void**)&Vhi, g_Vhi);
    cudaGetSymbolAddress((void**)&Vlo, g_Vlo);
    cudaGetSymbolAddress((void**)&Wihi, g_Wihi);
    cudaGetSymbolAddress((void**)&Wilo, g_Wilo);
    cudaGetSymbolAddress((void**)&WoVhi, g_WoVhi);
    cudaGetSymbolAddress((void**)&WoVlo, g_WoVlo);
    cudaGetSymbolAddress((void**)&WhHhi, g_WhHhi);
    cudaGetSymbolAddress((void**)&WhHlo, g_WhHlo);
    cudaGetSymbolAddress((void**)&WoHhi, g_WoHhi);
    cudaGetSymbolAddress((void**)&WoHlo, g_WoHlo);

    cudaFuncSetAttribute(tgemm_k, cudaFuncAttributeMaxDynamicSharedMemorySize, TG_SMEM);

    cudaStream_t st = 0;
    const int TB = 256;
    int zeroN = N_NODES * D_E;
    int NB = (N_NODES + 255) / 256;
    dim3 tgGrid((M + 127) / 128, 3);
    dim3 gemmGrid((M + 127) / 128, 3);
    int segGrid = (N_NODES * 32 + TB - 1) / TB;

    // ---- launches 1-4: put tgemm_k at position 4 for ncu visibility --------
    splitV_k<<<(M * KP_V + TB - 1) / TB, TB, 0, st>>>(V, M);                   // 1
    prepW_k<<<(NPADW * KP_V + TB - 1) / TB, TB, 0, st>>>(W_i, D_V, 0, D_V,
                                                          KP_V, Wihi, Wilo);  // 2
    prepW_k<<<(NPADW * KP_H + TB - 1) / TB, TB, 0, st>>>(W_h, D_H + D_E, 0, D_H,
                                                          KP_H, WhHhi, WhHlo); // 3
    tgemm_k<<<tgGrid, 256, TG_SMEM, st>>>(Vhi, Vlo, Wihi, Wilo, KP_V, KP_V / 32, M,
                                          b_i, nullptr, nullptr, 1, H0);      // 4 (profiled)

    // ---- remaining prep ----------------------------------------------------
    prepW_k<<<(NPADW * KP_V + TB - 1) / TB, TB, 0, st>>>(W_o, D_V + D_H, 0, D_V,
                                                          KP_V, WoVhi, WoVlo);
    prepW_k<<<(NPADW * KP_H + TB - 1) / TB, TB, 0, st>>>(W_o, D_V + D_H, D_V, D_H,
                                                          KP_H, WoHhi, WoHlo);
    detect_k<<<1, 32, 0, st>>>((const unsigned long long*)EI, nE);
    zero_k<<<(zeroN + TB - 1) / TB, TB, 0, st>>>();
    convert_hist_k<<<(nE + TB - 1) / TB, TB, 0, st>>>(EI, nE);
    scan1_k<<<NB, 256, 0, st>>>();
    scan2_k<<<1, 256, 0, st>>>(NB);
    scan3_k<<<NB, 256, 0, st>>>();
    csr_fill_k<<<(nE + TB - 1) / TB, TB, 0, st>>>(nE);
    se_scatter_k<<<(nE + TB - 1) / TB, TB, 0, st>>>(E, nE);

    // Ps = V @ W_oV^T + b_o
    tgemm_k<<<tgGrid, 256, TG_SMEM, st>>>(Vhi, Vlo, WoVhi, WoVlo, KP_V, KP_V / 32, M,
                                          b_o, nullptr, nullptr, 0, Ps);
    // Cs = SE @ W_hE^T + deg * b_h   (SIMT, K=14)
    sgemm_k<<<gemmGrid, TB, 0, st>>>(SE, D_E, M, W_h, D_H + D_E, D_H, b_h, deg, Cs);

    // layer 1: H = relu(H0 + segsum(H0[src]) @ W_hH^T + Cs)
    seg_sum_split_k<<<segGrid, TB, 0, st>>>(H0);
    tgemm_k<<<tgGrid, 256, TG_SMEM, st>>>(Ahi, Alo, WhHhi, WhHlo, KP_H, KP_H / 32, M,
                                          nullptr, H0, Cs, 1, Hs);
    // layer 2
    seg_sum_split_k<<<segGrid, TB, 0, st>>>(Hs);
    tgemm_k<<<tgGrid, 256, TG_SMEM, st>>>(Ahi, Alo, WhHhi, WhHlo, KP_H, KP_H / 32, M,
                                          nullptr, H0, Cs, 1, Hs);
    // final: out = relu(Ps + segsum(H[src]) @ W_oH^T)
    seg_sum_split_k<<<segGrid, TB, 0, st>>>(Hs);
    tgemm_k<<<tgGrid, 256, TG_SMEM, st>>>(Ahi, Alo, WoHhi, WoHlo, KP_H, KP_H / 32, M,
                                          nullptr, Ps, nullptr, 1, out);
}

// round 7
// speedup vs baseline: 1.8915x; 1.8915x over previous
#include <cuda_runtime.h>
#include <cuda_bf16.h>
#include <cstdint>
#include <cstddef>

#define N_NODES 50000
#define N_PADR  50048
#define N_EDGES_MAX 800000
#define D_V 133
#define D_E 14
#define D_H 300
#define GN  300
#define KP_V 160               // D_V padded to mult of 32
#define KP_H 320               // D_H padded to mult of 32
#define NPADW 384              // weight rows padded to 3*128

// ---------------- scratch (static device globals; no allocation) ------------
__device__ __align__(256) float g_H0[(size_t)N_NODES * D_H];
__device__ __align__(256) float g_Hs[(size_t)N_NODES * D_H];
__device__ __align__(256) float g_Cs[(size_t)N_NODES * D_H];
__device__ __align__(256) float g_Ps[(size_t)N_NODES * D_H];
__device__ __align__(256) float g_SE[(size_t)N_NODES * D_E];
__device__ __align__(256) __nv_bfloat16 g_Ahi[(size_t)N_PADR * KP_H];
__device__ __align__(256) __nv_bfloat16 g_Alo[(size_t)N_PADR * KP_H];
__device__ __align__(256) __nv_bfloat16 g_Vhi[(size_t)N_PADR * KP_V];
__device__ __align__(256) __nv_bfloat16 g_Vlo[(size_t)N_PADR * KP_V];
__device__ __align__(256) __nv_bfloat16 g_Wihi[NPADW * KP_V];
__device__ __align__(256) __nv_bfloat16 g_Wilo[NPADW * KP_V];
__device__ __align__(256) __nv_bfloat16 g_WoVhi[NPADW * KP_V];
__device__ __align__(256) __nv_bfloat16 g_WoVlo[NPADW * KP_V];
__device__ __align__(256) __nv_bfloat16 g_WhHhi[NPADW * KP_H];
__device__ __align__(256) __nv_bfloat16 g_WhHlo[NPADW * KP_H];
__device__ __align__(256) __nv_bfloat16 g_WoHhi[NPADW * KP_H];
__device__ __align__(256) __nv_bfloat16 g_WoHlo[NPADW * KP_H];
__device__ int   g_deg[N_NODES];
__device__ int   g_cnt[N_NODES];
__device__ int   g_rowptr[N_NODES + 1];
__device__ int   g_srcA[N_EDGES_MAX];
__device__ int   g_dstA[N_EDGES_MAX];
__device__ int   g_csr[N_EDGES_MAX];
__device__ int   g_blk[256];
__device__ int   g_blkoff[256];
__device__ int   g_is64;

// ======================= PTX helpers (family-safe only) =====================
__device__ __forceinline__ uint32_t s2u(const void* p) {
    uint32_t a;
    asm("{ .reg .u64 t; cvta.to.shared.u64 t, %1; cvt.u32.u64 %0, t; }"
        : "=r"(a) : "l"(p));
    return a;
}
#define CPA16(sa, ga) \
    asm volatile("cp.async.cg.shared.global [%0], [%1], 16;" :: "r"(sa), "l"(ga) : "memory")
#define CP_COMMIT() asm volatile("cp.async.commit_group;" ::: "memory")
template <int N>
__device__ __forceinline__ void cp_wait() {
    asm volatile("cp.async.wait_group %0;" :: "n"(N) : "memory");
}
#define LDSM_X4(r0, r1, r2, r3, addr) \
    asm volatile("ldmatrix.sync.aligned.m8n8.x4.shared.b16 {%0,%1,%2,%3}, [%4];" \
        : "=r"(r0), "=r"(r1), "=r"(r2), "=r"(r3) : "r"(addr))
#define MMA16816(d, a, b) \
    asm volatile("mma.sync.aligned.m16n8k16.row.col.f32.bf16.bf16.f32 " \
        "{%0,%1,%2,%3}, {%4,%5,%6,%7}, {%8,%9}, {%0,%1,%2,%3};" \
        : "+f"((d)[0]), "+f"((d)[1]), "+f"((d)[2]), "+f"((d)[3]) \
        : "r"((a)[0]), "r"((a)[1]), "r"((a)[2]), "r"((a)[3]), \
          "r"((b)[0]), "r"((b)[1]))

#define ROWB   80                  // smem row pitch (bytes) for 32-bf16 rows
#define MAT_B  (128 * ROWB)        // 10240 bytes per matrix tile
#define STAGE_B (4 * MAT_B)        // Ahi, Alo, Bhi, Blo
#define TG_SMEM (2 * STAGE_B)      // 81920 (2 CTAs/SM fit in 228KB)

// ======================= setup kernels ======================================
__global__ void detect_k(const unsigned long long* __restrict__ p, int n64) {
    if (blockIdx.x | threadIdx.x) return;
    int is64 = 1;
    int lim = n64 < 64 ? n64 : 64;
    for (int i = 0; i < lim; i++)
        if (p[i] >= (1ULL << 32)) { is64 = 0; break; }
    g_is64 = is64;
}

__global__ void zero_k() {
    int i = blockIdx.x * blockDim.x + threadIdx.x;
    if (i < N_NODES) { g_deg[i] = 0; g_cnt[i] = 0; }
    if (i < N_NODES * D_E) g_SE[i] = 0.f;
}

__global__ void convert_hist_k(const void* __restrict__ ei, int nE) {
    int e = blockIdx.x * blockDim.x + threadIdx.x;
    if (e >= nE) return;
    int s, d;
    if (g_is64) {
        const long long* p = (const long long*)ei;
        s = (int)p[e]; d = (int)p[nE + e];
    } else {
        const int* p = (const int*)ei;
        s = p[e]; d = p[nE + e];
    }
    g_srcA[e] = s;
    g_dstA[e] = d;
    atomicAdd(&g_deg[d], 1);
}

__global__ void scan1_k() {
    __shared__ int sm[256];
    int t = threadIdx.x, b = blockIdx.x;
    int i = b * 256 + t;
    sm[t] = (i < N_NODES) ? g_deg[i] : 0;
    __syncthreads();
    for (int off = 128; off; off >>= 1) {
        if (t < off) sm[t] += sm[t + off];
        __syncthreads();
    }
    if (t == 0) g_blk[b] = sm[0];
}
__global__ void scan2_k(int nb) {
    __shared__ int sm[256];
    int t = threadIdx.x;
    int v = (t < nb) ? g_blk[t] : 0;
    sm[t] = v;
    __syncthreads();
    for (int off = 1; off < 256; off <<= 1) {
        int u = (t >= off) ? sm[t - off] : 0;
        __syncthreads();
        sm[t] += u;
        __syncthreads();
    }
    if (t < nb) g_blkoff[t] = sm[t] - v;
}
__global__ void scan3_k() {
    __shared__ int sm[256];
    int t = threadIdx.x, b = blockIdx.x;
    int i = b * 256 + t;
    int v = (i < N_NODES) ? g_deg[i] : 0;
    sm[t] = v;
    __syncthreads();
    for (int off = 1; off < 256; off <<= 1) {
        int u = (t >= off) ? sm[t - off] : 0;
        __syncthreads();
        sm[t] += u;
        __syncthreads();
    }
    int excl = sm[t] - v + g_blkoff[b];
    if (i < N_NODES) g_rowptr[i] = excl;
    if (i == N_NODES - 1) g_rowptr[N_NODES] = excl + v;
}

__global__ void csr_fill_k(int nE) {
    int e = blockIdx.x * blockDim.x + threadIdx.x;
    if (e >= nE) return;
    int d = g_dstA[e];
    int pos = atomicAdd(&g_cnt[d], 1);
    g_csr[g_rowptr[d] + pos] = g_srcA[e];
}

__global__ void se_scatter_k(const float* __restrict__ E, int nE) {
    int e = blockIdx.x * blockDim.x + threadIdx.x;
    if (e >= nE) return;
    int d = g_dstA[e];
    float* base = &g_SE[(size_t)d * D_E];
    const float* src = &E[(size_t)e * D_E];
#pragma unroll
    for (int k = 0; k < D_E; k++) atomicAdd(base + k, src[k]);
}

// ======================= bf16 split helpers =================================
__device__ __forceinline__ void split4(float4 v, uint2& hi, uint2& lo) {
    __nv_bfloat16 hx = __float2bfloat16(v.x), hy = __float2bfloat16(v.y);
    __nv_bfloat16 hz = __float2bfloat16(v.z), hw = __float2bfloat16(v.w);
    __nv_bfloat16 lx = __float2bfloat16(v.x - __bfloat162float(hx));
    __nv_bfloat16 ly = __float2bfloat16(v.y - __bfloat162float(hy));
    __nv_bfloat16 lz = __float2bfloat16(v.z - __bfloat162float(hz));
    __nv_bfloat16 lw = __float2bfloat16(v.w - __bfloat162float(hw));
    hi.x = (uint32_t)__bfloat16_as_ushort(hx) | ((uint32_t)__bfloat16_as_ushort(hy) << 16);
    hi.y = (uint32_t)__bfloat16_as_ushort(hz) | ((uint32_t)__bfloat16_as_ushort(hw) << 16);
    lo.x = (uint32_t)__bfloat16_as_ushort(lx) | ((uint32_t)__bfloat16_as_ushort(ly) << 16);
    lo.y = (uint32_t)__bfloat16_as_ushort(lz) | ((uint32_t)__bfloat16_as_ushort(lw) << 16);
}

__global__ void splitV_k(const float* __restrict__ V, int M) {
    int idx = blockIdx.x * blockDim.x + threadIdx.x;
    if (idx >= M * KP_V) return;
    int m = idx / KP_V, k = idx - m * KP_V;
    float x = (k < D_V) ? V[(size_t)m * D_V + k] : 0.f;
    __nv_bfloat16 h = __float2bfloat16(x);
    g_Vhi[idx] = h;
    g_Vlo[idx] = __float2bfloat16(x - __bfloat162float(h));
}

__global__ void prepW_k(const float* __restrict__ W, int ldW, int colOff, int K,
                        int Kpad, __nv_bfloat16* __restrict__ hi,
                        __nv_bfloat16* __restrict__ lo) {
    int idx = blockIdx.x * blockDim.x + threadIdx.x;
    if (idx >= NPADW * Kpad) return;
    int n = idx / Kpad, k = idx - n * Kpad;
    float x = (n < GN && k < K) ? W[(size_t)n * ldW + colOff + k] : 0.f;
    __nv_bfloat16 h = __float2bfloat16(x);
    hi[idx] = h;
    lo[idx] = __float2bfloat16(x - __bfloat162float(h));
}

// ------- gather + segment-sum (float4 vectorized), emits bf16 hi/lo --------
__global__ __launch_bounds__(256) void seg_sum_split_k(const float* __restrict__ Hin) {
    int gw = (blockIdx.x * blockDim.x + threadIdx.x) >> 5;
    int lane = threadIdx.x & 31;
    if (gw >= N_NODES) return;
    int beg = g_rowptr[gw], end = g_rowptr[gw + 1];
    bool v2 = lane < 11;                      // float4 idx lane+64 < 75
    float4 a0 = {0.f, 0.f, 0.f, 0.f}, a1 = a0, a2 = a0;

    int i = beg;
    for (; i + 1 < end; i += 2) {
        const float4* r0 = (const float4*)(Hin + (size_t)g_csr[i] * D_H);
        const float4* r1 = (const float4*)(Hin + (size_t)g_csr[i + 1] * D_H);
        float4 x0 = __ldg(&r0[lane]),      y0 = __ldg(&r1[lane]);
        float4 x1 = __ldg(&r0[lane + 32]), y1 = __ldg(&r1[lane + 32]);
        a0.x += x0.x + y0.x; a0.y += x0.y + y0.y; a0.z += x0.z + y0.z; a0.w += x0.w + y0.w;
        a1.x += x1.x + y1.x; a1.y += x1.y + y1.y; a1.z += x1.z + y1.z; a1.w += x1.w + y1.w;
        if (v2) {
            float4 x2 = __ldg(&r0[lane + 64]), y2 = __ldg(&r1[lane + 64]);
            a2.x += x2.x + y2.x; a2.y += x2.y + y2.y;
            a2.z += x2.z + y2.z; a2.w += x2.w + y2.w;
        }
    }
    if (i < end) {
        const float4* r0 = (const float4*)(Hin + (size_t)g_csr[i] * D_H);
        float4 x0 = __ldg(&r0[lane]), x1 = __ldg(&r0[lane + 32]);
        a0.x += x0.x; a0.y += x0.y; a0.z += x0.z; a0.w += x0.w;
        a1.x += x1.x; a1.y += x1.y; a1.z += x1.z; a1.w += x1.w;
        if (v2) {
            float4 x2 = __ldg(&r0[lane + 64]);
            a2.x += x2.x; a2.y += x2.y; a2.z += x2.z; a2.w += x2.w;
        }
    }

    size_t o = (size_t)gw * KP_H;
    uint2* Hv = (uint2*)(g_Ahi + o);
    uint2* Lv = (uint2*)(g_Alo + o);
    uint2 h, l;
    split4(a0, h, l); Hv[lane] = h;      Lv[lane] = l;
    split4(a1, h, l); Hv[lane + 32] = h; Lv[lane + 32] = l;
    if (v2) { split4(a2, h, l); Hv[lane + 64] = h; Lv[lane + 64] = l; }
    else if (lane < 16) {
        uint2 z = {0u, 0u};
        Hv[lane + 64] = z; Lv[lane + 64] = z;
    }
}

// ======================= SIMT SGEMM (only for Cs, K=14) =====================
__global__ __launch_bounds__(256) void sgemm_k(
    const float* __restrict__ X, int K, int M,
    const float* __restrict__ W, int ldW, int colOff,
    const float* __restrict__ bias, const int* __restrict__ degv,
    float* __restrict__ Out)
{
    __shared__ __align__(16) float As[8][128];
    __shared__ __align__(16) float Bs[8][128];
    int tid = threadIdx.x;
    int m0 = blockIdx.x * 128;
    int n0 = blockIdx.y * 128;
    int xr = tid >> 3, xc = tid & 7;
    int tx = tid & 15, ty = tid >> 4;
    int mA = ty * 4, mB = 64 + ty * 4;
    int nA = tx * 4, nB = 64 + tx * 4;
    float acc[8][8] = {};

    for (int k0 = 0; k0 < K; k0 += 8) {
#pragma unroll
        for (int i = 0; i < 4; i++) {
            int m = xr + i * 32;
            int gm = m0 + m, gk = k0 + xc;
            As[xc][m] = (gm < M && gk < K) ? X[(size_t)gm * K + gk] : 0.f;
        }
#pragma unroll
        for (int i = 0; i < 4; i++) {
            int n = xr + i * 32;
            int gn = n0 + n, gk = k0 + xc;
            Bs[xc][n] = (gn < GN && gk < K) ? W[(size_t)gn * ldW + colOff + gk] : 0.f;
        }
        __syncthreads();
#pragma unroll
        for (int k = 0; k < 8; k++) {
            float4 q0 = *(const float4*)&As[k][mA];
            float4 q1 = *(const float4*)&As[k][mB];
            float4 b0 = *(const float4*)&Bs[k][nA];
            float4 b1 = *(const float4*)&Bs[k][nB];
            float av[8] = {q0.x, q0.y, q0.z, q0.w, q1.x, q1.y, q1.z, q1.w};
            float bv[8] = {b0.x, b0.y, b0.z, b0.w, b1.x, b1.y, b1.z, b1.w};
#pragma unroll
            for (int i = 0; i < 8; i++)
#pragma unroll
                for (int j = 0; j < 8; j++)
                    acc[i][j] += av[i] * bv[j];
        }
        __syncthreads();
    }
#pragma unroll
    for (int i = 0; i < 8; i++) {
        int m = m0 + ((i < 4) ? (ty * 4 + i) : (64 + ty * 4 + (i - 4)));
        if (m >= M) continue;
        float degf = degv ? (float)degv[m] : 1.f;
#pragma unroll
        for (int j = 0; j < 8; j++) {
            int n = n0 + ((j < 4) ? (tx * 4 + j) : (64 + tx * 4 + (j - 4)));
            if (n >= GN) continue;
            float v = acc[i][j] + degf * bias[n];
            Out[(size_t)m * GN + n] = v;
        }
    }
}

// ======================= HMMA bf16x3 GEMM ===================================
// __launch_bounds__(256, 2): force <=128 regs so 2 CTAs/SM hide pipe latency.
__global__ void __launch_bounds__(256, 2) tgemm_k(
    const __nv_bfloat16* __restrict__ Xhi, const __nv_bfloat16* __restrict__ Xlo,
    const __nv_bfloat16* __restrict__ Whi, const __nv_bfloat16* __restrict__ Wlo,
    int Kpad, int nchunks, int M,
    const float* __restrict__ bias, const float* __restrict__ add1,
    const float* __restrict__ add2, int relu, float* __restrict__ Out)
{
    extern __shared__ __align__(16) char smem[];
    uint32_t sb = s2u(smem);
    int tid = threadIdx.x, wid = tid >> 5, lane = tid & 31;
    int wm = wid >> 2, wn = wid & 3;       // 2 x 4 warp grid, warp tile 64x32
    int m0 = blockIdx.x * 128, n0 = blockIdx.y * 128;

    size_t ldb = (size_t)Kpad * 2;
    const char* gsrc[4];
    gsrc[0] = (const char*)(Xhi + (size_t)m0 * Kpad);
    gsrc[1] = (const char*)(Xlo + (size_t)m0 * Kpad);
    gsrc[2] = (const char*)(Whi + (size_t)n0 * Kpad);
    gsrc[3] = (const char*)(Wlo + (size_t)n0 * Kpad);

    float acc[4][4][4] = {};

#define LOAD_STAGE(s, c)                                                       \
    do {                                                                       \
        uint32_t _base = sb + (uint32_t)(s) * STAGE_B;                         \
        _Pragma("unroll")                                                      \
        for (int _t = 0; _t < 8; _t++) {                                       \
            int _id = _t * 256 + tid;                                          \
            int _mat = _id >> 9;                                               \
            int _r = (_id >> 2) & 127;                                         \
            int _q = _id & 3;                                                  \
            uint32_t _so = _base + _mat * MAT_B + _r * ROWB + _q * 16;         \
            const char* _g = gsrc[_mat] + (size_t)_r * ldb + (c) * 64 + _q * 16; \
            CPA16(_so, _g);                                                    \
        }                                                                      \
    } while (0)

    LOAD_STAGE(0, 0);
    CP_COMMIT();

    for (int i = 0; i < nchunks; i++) {
        if (i + 1 < nchunks) {
            LOAD_STAGE((i + 1) & 1, i + 1);
            CP_COMMIT();
            cp_wait<1>();
        } else {
            cp_wait<0>();
        }
        __syncthreads();
        uint32_t stb = sb + (uint32_t)(i & 1) * STAGE_B;

#pragma unroll
        for (int kk = 0; kk < 2; kk++) {
            int k0 = kk * 16;
            int ar = lane & 7, sel = lane >> 3;
            int arow = ((sel & 1) ? 8 : 0) + ar;
            int akof = (k0 + ((sel >> 1) ? 8 : 0)) * 2;
            int brow = ((sel >> 1) ? 8 : 0) + ar;
            int bkof = (k0 + ((sel & 1) ? 8 : 0)) * 2;

            uint32_t ah[4][4], bh[4][2], bl[4][2];
#pragma unroll
            for (int mt = 0; mt < 4; mt++) {
                uint32_t ad = stb + (wm * 64 + mt * 16 + arow) * ROWB + akof;
                LDSM_X4(ah[mt][0], ah[mt][1], ah[mt][2], ah[mt][3], ad);
            }
#pragma unroll
            for (int p = 0; p < 2; p++) {
                uint32_t bd = stb + 2 * MAT_B + (wn * 32 + p * 16 + brow) * ROWB + bkof;
                uint32_t r0, r1, r2, r3;
                LDSM_X4(r0, r1, r2, r3, bd);
                bh[p * 2][0] = r0; bh[p * 2][1] = r1;
                bh[p * 2 + 1][0] = r2; bh[p * 2 + 1][1] = r3;
                LDSM_X4(r0, r1, r2, r3, bd + MAT_B);
                bl[p * 2][0] = r0; bl[p * 2][1] = r1;
                bl[p * 2 + 1][0] = r2; bl[p * 2 + 1][1] = r3;
            }
            // hi x hi  and  hi x lo  while al regs are not yet live
#pragma unroll
            for (int mt = 0; mt < 4; mt++)
#pragma unroll
                for (int nt = 0; nt < 4; nt++) {
                    MMA16816(acc[mt][nt], ah[mt], bh[nt]);
                    MMA16816(acc[mt][nt], ah[mt], bl[nt]);
                }
            // lo x hi in its own register scope (reuses ah's slots)
            {
                uint32_t al[4][4];
#pragma unroll
                for (int mt = 0; mt < 4; mt++) {
                    uint32_t ad = stb + (wm * 64 + mt * 16 + arow) * ROWB + akof;
                    LDSM_X4(al[mt][0], al[mt][1], al[mt][2], al[mt][3], ad + MAT_B);
                }
#pragma unroll
                for (int mt = 0; mt < 4; mt++)
#pragma unroll
                    for (int nt = 0; nt < 4; nt++)
                        MMA16816(acc[mt][nt], al[mt], bh[nt]);
            }
        }
        __syncthreads();
    }
#undef LOAD_STAGE

    float* Ds = (float*)smem;          // 128 x 136 floats
    int g = lane >> 2, tg = lane & 3;
#pragma unroll
    for (int mt = 0; mt < 4; mt++)
#pragma unroll
        for (int nt = 0; nt < 4; nt++) {
            int row = wm * 64 + mt * 16 + g;
            int col = wn * 32 + nt * 8 + tg * 2;
            Ds[row * 136 + col]           = acc[mt][nt][0];
            Ds[row * 136 + col + 1]       = acc[mt][nt][1];
            Ds[(row + 8) * 136 + col]     = acc[mt][nt][2];
            Ds[(row + 8) * 136 + col + 1] = acc[mt][nt][3];
        }
    __syncthreads();

    int col = tid & 127, rh = tid >> 7;
    int n = n0 + col;
    bool nv = n < GN;
    float bv = (bias && nv) ? bias[n] : 0.f;
    for (int r = rh * 64; r < rh * 64 + 64; r++) {
        int gm = m0 + r;
        if (gm >= M) break;
        if (nv) {
            float v = Ds[r * 136 + col] + bv;
            if (add1) v += add1[(size_t)gm * GN + n];
            if (add2) v += add2[(size_t)gm * GN + n];
            if (relu) v = fmaxf(v, 0.f);
            Out[(size_t)gm * GN + n] = v;
        }
    }
}

// ======================= host orchestration =================================
extern "C" void kernel_launch(void* const* d_in, const int* in_sizes, int n_in,
                              void* d_out, int out_size) {
    const float* V   = (const float*)d_in[0];
    const float* E   = (const float*)d_in[1];
    const void*  EI  = d_in[2];
    const float* W_i = (const float*)d_in[3];
    const float* b_i = (const float*)d_in[4];
    const float* W_h = (const float*)d_in[5];
    const float* b_h = (const float*)d_in[6];
    const float* W_o = (const float*)d_in[7];
    const float* b_o = (const float*)d_in[8];
    float* out = (float*)d_out;

    int nE = in_sizes[2] / 2;
    int M  = in_sizes[0] / D_V;   // 50000

    float *H0, *Hs, *Cs, *Ps, *SE;
    int *deg;
    __nv_bfloat16 *Ahi, *Alo, *Vhi, *Vlo;
    __nv_bfloat16 *Wihi, *Wilo, *WoVhi, *WoVlo, *WhHhi, *WhHlo, *WoHhi, *WoHlo;
    cudaGetSymbolAddress((void**)&H0, g_H0);
    cudaGetSymbolAddress((void**)&Hs, g_Hs);
    cudaGetSymbolAddress((void**)&Cs, g_Cs);
    cudaGetSymbolAddress((void**)&Ps, g_Ps);
    cudaGetSymbolAddress((void**)&SE, g_SE);
    cudaGetSymbolAddress((void**)&deg, g_deg);
    cudaGetSymbolAddress((void**)&Ahi, g_Ahi);
    cudaGetSymbolAddress((void**)&Alo, g_Alo);
    cudaGetSymbolAddress((void**)&Vhi, g_Vhi);
    cudaGetSymbolAddress((void**)&Vlo, g_Vlo);
    cudaGetSymbolAddress((void**)&Wihi, g_Wihi);
    cudaGetSymbolAddress((void**)&Wilo, g_Wilo);
    cudaGetSymbolAddress((void**)&WoVhi, g_WoVhi);
    cudaGetSymbolAddress((void**)&WoVlo, g_WoVlo);
    cudaGetSymbolAddress((void**)&WhHhi, g_WhHhi);
    cudaGetSymbolAddress((void**)&WhHlo, g_WhHlo);
    cudaGetSymbolAddress((void**)&WoHhi, g_WoHhi);
    cudaGetSymbolAddress((void**)&WoHlo, g_WoHlo);

    cudaFuncSetAttribute(tgemm_k, cudaFuncAttributeMaxDynamicSharedMemorySize, TG_SMEM);

    cudaStream_t st = 0;
    const int TB = 256;
    int zeroN = N_NODES * D_E;
    int NB = (N_NODES + 255) / 256;
    dim3 tgGrid((M + 127) / 128, 3);
    dim3 gemmGrid((M + 127) / 128, 3);
    int segGrid = (N_NODES * 32 + TB - 1) / TB;

    // ---- launches 1-4: keep tgemm_k at position 4 for ncu visibility -------
    splitV_k<<<(M * KP_V + TB - 1) / TB, TB, 0, st>>>(V, M);                   // 1
    prepW_k<<<(NPADW * KP_V + TB - 1) / TB, TB, 0, st>>>(W_i, D_V, 0, D_V,
                                                          KP_V, Wihi, Wilo);  // 2
    prepW_k<<<(NPADW * KP_H + TB - 1) / TB, TB, 0, st>>>(W_h, D_H + D_E, 0, D_H,
                                                          KP_H, WhHhi, WhHlo); // 3
    tgemm_k<<<tgGrid, 256, TG_SMEM, st>>>(Vhi, Vlo, Wihi, Wilo, KP_V, KP_V / 32, M,
                                          b_i, nullptr, nullptr, 1, H0);      // 4 (profiled)

    // ---- remaining prep ----------------------------------------------------
    prepW_k<<<(NPADW * KP_V + TB - 1) / TB, TB, 0, st>>>(W_o, D_V + D_H, 0, D_V,
                                                          KP_V, WoVhi, WoVlo);
    prepW_k<<<(NPADW * KP_H + TB - 1) / TB, TB, 0, st>>>(W_o, D_V + D_H, D_V, D_H,
                                                          KP_H, WoHhi, WoHlo);
    detect_k<<<1, 32, 0, st>>>((const unsigned long long*)EI, nE);
    zero_k<<<(zeroN + TB - 1) / TB, TB, 0, st>>>();
    convert_hist_k<<<(nE + TB - 1) / TB, TB, 0, st>>>(EI, nE);
    scan1_k<<<NB, 256, 0, st>>>();
    scan2_k<<<1, 256, 0, st>>>(NB);
    scan3_k<<<NB, 256, 0, st>>>();
    csr_fill_k<<<(nE + TB - 1) / TB, TB, 0, st>>>(nE);
    se_scatter_k<<<(nE + TB - 1) / TB, TB, 0, st>>>(E, nE);

    // Ps = V @ W_oV^T + b_o
    tgemm_k<<<tgGrid, 256, TG_SMEM, st>>>(Vhi, Vlo, WoVhi, WoVlo, KP_V, KP_V / 32, M,
                                          b_o, nullptr, nullptr, 0, Ps);
    // Cs = SE @ W_hE^T + deg * b_h   (SIMT, K=14)
    sgemm_k<<<gemmGrid, TB, 0, st>>>(SE, D_E, M, W_h, D_H + D_E, D_H, b_h, deg, Cs);

    // layer 1: H = relu(H0 + segsum(H0[src]) @ W_hH^T + Cs)
    seg_sum_split_k<<<segGrid, TB, 0, st>>>(H0);
    tgemm_k<<<tgGrid, 256, TG_SMEM, st>>>(Ahi, Alo, WhHhi, WhHlo, KP_H, KP_H / 32, M,
                                          nullptr, H0, Cs, 1, Hs);
    // layer 2
    seg_sum_split_k<<<segGrid, TB, 0, st>>>(Hs);
    tgemm_k<<<tgGrid, 256, TG_SMEM, st>>>(Ahi, Alo, WhHhi, WhHlo, KP_H, KP_H / 32, M,
                                          nullptr, H0, Cs, 1, Hs);
    // final: out = relu(Ps + segsum(H[src]) @ W_oH^T)
    seg_sum_split_k<<<segGrid, TB, 0, st>>>(Hs);
    tgemm_k<<<tgGrid, 256, TG_SMEM, st>>>(Ahi, Alo, WoHhi, WoHlo, KP_H, KP_H / 32, M,
                                          nullptr, Ps, nullptr, 1, out);
}